// round 6
// baseline (speedup 1.0000x reference)
#include <cuda_runtime.h>
#include <math.h>

#define CC   16
#define DIMN 16
#define LL   6

typedef unsigned long long u64;

// ---------------- device-global precomputed params ----------------
__device__ ulonglong2 g_negD2[LL * CC * 4];  // -(z0_l - z0_{l-1}), f32x2 pairs; l=0: -z0_0
__device__ ulonglong2 g_m52[CC * 4];         // z0_5 - mean, f32x2 pairs
__device__ ulonglong2 g_parab[LL * 8];       // {alpha2, beta2} packed per c-pair
__device__ u64        g_parc[LL * 8];        // alpha*beta packed per c-pair
__device__ u64        g_hld2[8];             // half_logdet packed per c-pair
__device__ float      g_hld[CC];
__device__ float      g_Linv[CC * DIMN * DIMN];
__device__ int        g_ident;

// ---------------- f32x2 packed helpers (sm_103a) -------------------
__device__ __forceinline__ u64 pk2(float lo, float hi) {
    u64 r; asm("mov.b64 %0, {%1, %2};" : "=l"(r) : "f"(lo), "f"(hi)); return r;
}
__device__ __forceinline__ void up2(float& lo, float& hi, u64 v) {
    asm("mov.b64 {%0, %1}, %2;" : "=f"(lo), "=f"(hi) : "l"(v));
}
__device__ __forceinline__ u64 ffma2(u64 a, u64 b, u64 c) {
    u64 d; asm("fma.rn.f32x2 %0, %1, %2, %3;" : "=l"(d) : "l"(a), "l"(b), "l"(c)); return d;
}
__device__ __forceinline__ u64 add2(u64 a, u64 b) {
    u64 d; asm("add.rn.f32x2 %0, %1, %2;" : "=l"(d) : "l"(a), "l"(b)); return d;
}
__device__ __forceinline__ u64 mul2(u64 a, u64 b) {
    u64 d; asm("mul.rn.f32x2 %0, %1, %2;" : "=l"(d) : "l"(a), "l"(b)); return d;
}
__device__ __forceinline__ float fast_sqrt(float x) {
    float r; asm("sqrt.approx.f32 %0, %1;" : "=f"(r) : "f"(x)); return r;
}
__device__ __forceinline__ float fast_rcp(float x) {
    float r; asm("rcp.approx.f32 %0, %1;" : "=f"(r) : "f"(x)); return r;
}
__device__ __forceinline__ float hsum2(u64 a, u64 b) {
    u64 e = add2(a, b);
    float lo, hi; up2(lo, hi, e);
    return lo + hi;
}

// packed per-layer scalar tail for a c-pair; returns f1 pair
__device__ __forceinline__ u64 layer_tail(u64 e0A, u64 e1A, u64 e0B, u64 e1B,
                                          u64 a2, u64 b2, u64 ab2,
                                          u64& P1p, u64& P2p) {
    const u64 ONE2 = pk2(1.0f, 1.0f);
    float r2A = hsum2(e0A, e1A);
    float r2B = hsum2(e0B, e1B);
    float rA = fast_sqrt(r2A), rB = fast_sqrt(r2B);
    u64 rp = pk2(rA, rB);
    u64 upad = add2(a2, rp);                 // alpha + r
    float uA, uB; up2(uA, uB, upad);
    u64 hp = pk2(fast_rcp(uA), fast_rcp(uB));
    u64 f1p = ffma2(b2, hp, ONE2);           // 1 + beta*h
    u64 hh  = mul2(hp, hp);
    u64 f2p = ffma2(ab2, hh, ONE2);          // 1 + alpha*beta*h^2
    P1p = mul2(P1p, f1p);
    P2p = mul2(P2p, f2p);
    return f1p;
}

// ---------------- setup kernel ----------------
__global__ void setup_kernel(const float* __restrict__ la, const float* __restrict__ be,
                             const float* __restrict__ z0, const float* __restrict__ mean,
                             const float* __restrict__ cov) {
    __shared__ int s_bad;
    int t = threadIdx.x;
    if (t == 0) s_bad = 0;
    __syncthreads();

    // packed params per (layer, c-pair)
    for (int i = t; i < LL * 8; i += 256) {
        int l = i / 8, cp = i % 8;
        int c0 = 2 * cp, c1 = c0 + 1;
        float a0 = expf(la[l * CC + c0]), a1 = expf(la[l * CC + c1]);
        float b0 = be[l * CC + c0],       b1 = be[l * CC + c1];
        ulonglong2 v; v.x = pk2(a0, a1); v.y = pk2(b0, b1);
        g_parab[i] = v;
        g_parc[i]  = pk2(a0 * b0, a1 * b1);
    }
    // layer deltas
    for (int i = t; i < LL * CC * 4; i += 256) {
        int l = i / (CC * 4), rem = i % (CC * 4), c = rem / 4, j = rem % 4;
        int base = (l * CC + c) * DIMN + 4 * j;
        float d0 = -z0[base], d1 = -z0[base + 1], d2 = -z0[base + 2], d3 = -z0[base + 3];
        if (l > 0) {
            int pb = ((l - 1) * CC + c) * DIMN + 4 * j;
            d0 += z0[pb]; d1 += z0[pb + 1]; d2 += z0[pb + 2]; d3 += z0[pb + 3];
        }
        ulonglong2 v; v.x = pk2(d0, d1); v.y = pk2(d2, d3);
        g_negD2[i] = v;
    }
    // final offset: z0_5 - mean
    for (int i = t; i < CC * 4; i += 256) {
        int c = i / 4, j = i % 4;
        int b5 = (5 * CC + c) * DIMN + 4 * j;
        int mb = c * DIMN + 4 * j;
        ulonglong2 v;
        v.x = pk2(z0[b5]     - mean[mb],     z0[b5 + 1] - mean[mb + 1]);
        v.y = pk2(z0[b5 + 2] - mean[mb + 2], z0[b5 + 3] - mean[mb + 3]);
        g_m52[i] = v;
    }

    int bad = 0;
    for (int i = t; i < CC * DIMN * DIMN; i += 256) {
        float e = (((i % (DIMN * DIMN)) % (DIMN + 1)) == 0) ? 1.0f : 0.0f;
        if (cov[i] != e) bad = 1;
    }
    if (bad) atomicOr(&s_bad, 1);
    __syncthreads();
    int id = (s_bad == 0) ? 1 : 0;
    if (t == 0) g_ident = id;

    int c = t;
    if (c < CC) {
        if (id) {
            g_hld[c] = 0.0f;
        } else {
            // general Cholesky + triangular inverse (cold path)
            float Lm[DIMN][DIMN];
            const float* A = cov + c * DIMN * DIMN;
            #pragma unroll 1
            for (int j = 0; j < DIMN; j++) {
                float s = A[j * DIMN + j];
                #pragma unroll 1
                for (int k = 0; k < j; k++) s -= Lm[j][k] * Lm[j][k];
                float d = sqrtf(s);
                Lm[j][j] = d;
                float inv = 1.0f / d;
                #pragma unroll 1
                for (int i = j + 1; i < DIMN; i++) {
                    float s2 = A[i * DIMN + j];
                    #pragma unroll 1
                    for (int k = 0; k < j; k++) s2 -= Lm[i][k] * Lm[j][k];
                    Lm[i][j] = s2 * inv;
                }
            }
            float hld = 0.0f;
            #pragma unroll 1
            for (int j = 0; j < DIMN; j++) hld += logf(Lm[j][j]);
            g_hld[c] = hld;

            float Li[DIMN][DIMN];
            #pragma unroll 1
            for (int j = 0; j < DIMN; j++) {
                for (int i = 0; i < DIMN; i++) Li[i][j] = 0.0f;
                Li[j][j] = 1.0f / Lm[j][j];
                #pragma unroll 1
                for (int i = j + 1; i < DIMN; i++) {
                    float s3 = 0.0f;
                    #pragma unroll 1
                    for (int k = j; k < i; k++) s3 += Lm[i][k] * Li[k][j];
                    Li[i][j] = -s3 / Lm[i][i];
                }
            }
            for (int i = 0; i < DIMN; i++)
                for (int j = 0; j < DIMN; j++)
                    g_Linv[(c * DIMN + i) * DIMN + j] = Li[i][j];
        }
    }
    __syncthreads();
    if (t < 8) g_hld2[t] = pk2(g_hld[2 * t], g_hld[2 * t + 1]);
}

// ---------------- main density kernel ----------------
__global__ void __launch_bounds__(128, 8)
density_kernel(const float* __restrict__ z, float* __restrict__ out, int N)
{
    __shared__ ulonglong2 s_negD2[LL * CC * 4];   // 6 KB
    __shared__ ulonglong2 s_m52[CC * 4];          // 1 KB
    __shared__ ulonglong2 s_parab[LL * 8];        // 768 B
    __shared__ u64        s_parc[LL * 8];         // 384 B
    __shared__ u64        s_hld2[8];
    __shared__ float      s_Linv[CC * DIMN * DIMN]; // 16 KB (used only if !ident)

    int t = threadIdx.x;
    for (int i = t; i < LL * CC * 4; i += 128) s_negD2[i] = g_negD2[i];
    for (int i = t; i < CC * 4; i += 128)      s_m52[i]   = g_m52[i];
    if (t < LL * 8) { s_parab[t] = g_parab[t]; s_parc[t] = g_parc[t]; }
    if (t < 8) s_hld2[t] = g_hld2[t];
    int ident = g_ident;
    if (!ident)
        for (int i = t; i < CC * DIMN * DIMN; i += 128) s_Linv[i] = g_Linv[i];
    __syncthreads();

    int n = blockIdx.x * 128 + t;
    if (n >= N) return;

    const float4* zr = (const float4*)(z + (size_t)n * DIMN);
    const float HALF_DIM_LOG2PI = 14.7030165f;   // 0.5 * 16 * log(2*pi)
    float2* op = (float2*)(out + (size_t)n * CC);

    #pragma unroll 1
    for (int cp = 0; cp < 8; cp++) {
        const int c0 = 2 * cp;
        const ulonglong2* dA = &s_negD2[c0 * 4];      // layer stride: CC*4 = 64
        const ulonglong2* dB = dA + 4;

        u64 sA[8], sB[8];
        u64 P1p = pk2(1.0f, 1.0f), P2p = P1p;
        u64 e0A = 0ull, e1A = 0ull, e0B = 0ull, e1B = 0ull;

        // ---- layer 0: s = z - z0_0 (z reloaded from L1; registers freed after) ----
        {
            float4 q0 = __ldg(zr), q1 = __ldg(zr + 1), q2 = __ldg(zr + 2), q3 = __ldg(zr + 3);
            u64 zb[8];
            zb[0] = pk2(q0.x, q0.y); zb[1] = pk2(q0.z, q0.w);
            zb[2] = pk2(q1.x, q1.y); zb[3] = pk2(q1.z, q1.w);
            zb[4] = pk2(q2.x, q2.y); zb[5] = pk2(q2.z, q2.w);
            zb[6] = pk2(q3.x, q3.y); zb[7] = pk2(q3.z, q3.w);
            #pragma unroll
            for (int j = 0; j < 4; j++) {
                ulonglong2 da = dA[j], db = dB[j];
                sA[2 * j]     = add2(zb[2 * j],     da.x);
                sA[2 * j + 1] = add2(zb[2 * j + 1], da.y);
                sB[2 * j]     = add2(zb[2 * j],     db.x);
                sB[2 * j + 1] = add2(zb[2 * j + 1], db.y);
                e0A = ffma2(sA[2 * j],     sA[2 * j],     e0A);
                e1A = ffma2(sA[2 * j + 1], sA[2 * j + 1], e1A);
                e0B = ffma2(sB[2 * j],     sB[2 * j],     e0B);
                e1B = ffma2(sB[2 * j + 1], sB[2 * j + 1], e1B);
            }
        }
        ulonglong2 pab = s_parab[cp];
        u64 f1p = layer_tail(e0A, e1A, e0B, e1B, pab.x, pab.y, s_parc[cp], P1p, P2p);
        float f1A, f1B; up2(f1A, f1B, f1p);
        u64 f1A2 = pk2(f1A, f1A), f1B2 = pk2(f1B, f1B);

        // ---- layers 1..5: s' = f1*s - (z0_l - z0_{l-1}) ----
        #pragma unroll
        for (int l = 1; l < LL; l++) {
            const ulonglong2* dAl = dA + l * 64;
            const ulonglong2* dBl = dB + l * 64;
            e0A = 0ull; e1A = 0ull; e0B = 0ull; e1B = 0ull;
            #pragma unroll
            for (int j = 0; j < 4; j++) {
                ulonglong2 da = dAl[j], db = dBl[j];
                sA[2 * j]     = ffma2(f1A2, sA[2 * j],     da.x);
                sA[2 * j + 1] = ffma2(f1A2, sA[2 * j + 1], da.y);
                sB[2 * j]     = ffma2(f1B2, sB[2 * j],     db.x);
                sB[2 * j + 1] = ffma2(f1B2, sB[2 * j + 1], db.y);
                e0A = ffma2(sA[2 * j],     sA[2 * j],     e0A);
                e1A = ffma2(sA[2 * j + 1], sA[2 * j + 1], e1A);
                e0B = ffma2(sB[2 * j],     sB[2 * j],     e0B);
                e1B = ffma2(sB[2 * j + 1], sB[2 * j + 1], e1B);
            }
            pab = s_parab[l * 8 + cp];
            f1p = layer_tail(e0A, e1A, e0B, e1B, pab.x, pab.y, s_parc[l * 8 + cp], P1p, P2p);
            up2(f1A, f1B, f1p);
            f1A2 = pk2(f1A, f1A); f1B2 = pk2(f1B, f1B);
        }

        // ---- final: diff = zK - mean = f1_5*s_5 + (z0_5 - mean) ----
        const ulonglong2* mA = &s_m52[c0 * 4];
        const ulonglong2* mB = mA + 4;
        float qA, qB;
        if (ident) {
            u64 a0 = 0ull, a1 = 0ull, b0 = 0ull, b1 = 0ull;
            #pragma unroll
            for (int j = 0; j < 4; j++) {
                ulonglong2 ma = mA[j], mb = mB[j];
                u64 dx = ffma2(f1A2, sA[2 * j],     ma.x);
                u64 dy = ffma2(f1A2, sA[2 * j + 1], ma.y);
                u64 ex = ffma2(f1B2, sB[2 * j],     mb.x);
                u64 ey = ffma2(f1B2, sB[2 * j + 1], mb.y);
                a0 = ffma2(dx, dx, a0); a1 = ffma2(dy, dy, a1);
                b0 = ffma2(ex, ex, b0); b1 = ffma2(ey, ey, b1);
            }
            qA = hsum2(a0, a1);
            qB = hsum2(b0, b1);
        } else {
            float drA[DIMN], drB[DIMN];
            #pragma unroll
            for (int j = 0; j < 4; j++) {
                ulonglong2 ma = mA[j], mb = mB[j];
                u64 dx = ffma2(f1A2, sA[2 * j],     ma.x);
                u64 dy = ffma2(f1A2, sA[2 * j + 1], ma.y);
                u64 ex = ffma2(f1B2, sB[2 * j],     mb.x);
                u64 ey = ffma2(f1B2, sB[2 * j + 1], mb.y);
                up2(drA[4 * j],     drA[4 * j + 1], dx);
                up2(drA[4 * j + 2], drA[4 * j + 3], dy);
                up2(drB[4 * j],     drB[4 * j + 1], ex);
                up2(drB[4 * j + 2], drB[4 * j + 3], ey);
            }
            qA = 0.0f; qB = 0.0f;
            const float* LpA = &s_Linv[c0 * DIMN * DIMN];
            const float* LpB = LpA + DIMN * DIMN;
            #pragma unroll 1
            for (int j = 0; j < DIMN; j++) {
                float sa = 0.0f, sb = 0.0f;
                #pragma unroll 1
                for (int i = 0; i <= j; i++) {
                    sa = fmaf(LpA[j * DIMN + i], drA[i], sa);
                    sb = fmaf(LpB[j * DIMN + i], drB[i], sb);
                }
                qA = fmaf(sa, sa, qA);
                qB = fmaf(sb, sb, qB);
            }
        }

        // log_det_jac total = log(P1^15 * P2), packed pow15
        u64 p2  = mul2(P1p, P1p);
        u64 p4  = mul2(p2, p2);
        u64 p8  = mul2(p4, p4);
        u64 p15 = mul2(mul2(p8, p4), mul2(p2, P1p));
        u64 g   = mul2(p15, P2p);
        float gA, gB; up2(gA, gB, g);
        float hldA, hldB; up2(hldA, hldB, s_hld2[cp]);
        float vA = fmaf(-0.5f, qA, -HALF_DIM_LOG2PI) - hldA + __logf(gA);
        float vB = fmaf(-0.5f, qB, -HALF_DIM_LOG2PI) - hldB + __logf(gB);
        if (vA != vA) vA = __int_as_float(0xff800000);  // NaN -> -inf
        if (vB != vB) vB = __int_as_float(0xff800000);
        op[cp] = make_float2(vA, vB);
    }
}

// ---------------- launch ----------------
extern "C" void kernel_launch(void* const* d_in, const int* in_sizes, int n_in,
                              void* d_out, int out_size) {
    const float* z    = (const float*)d_in[0];
    const float* z0   = (const float*)d_in[1];
    const float* la   = (const float*)d_in[2];
    const float* be   = (const float*)d_in[3];
    const float* mean = (const float*)d_in[4];
    const float* cov  = (const float*)d_in[5];
    float* out = (float*)d_out;

    int N = in_sizes[0] / DIMN;

    setup_kernel<<<1, 256>>>(la, be, z0, mean, cov);
    int blocks = (N + 127) / 128;
    density_kernel<<<blocks, 128>>>(z, out, N);
}

// round 7
// speedup vs baseline: 1.0525x; 1.0525x over previous
#include <cuda_runtime.h>
#include <math.h>

#define CC   16
#define DIMN 16
#define LL   6

typedef unsigned long long u64;

// ---------------- device-global precomputed params ----------------
// Deltas interleaved by c-pair: entry (l,cp,j) holds dims {2j,2j+1} for c0=2cp,c1=2cp+1:
//   .x = ( -D_l[c0][2j],   -D_l[c1][2j]   )
//   .y = ( -D_l[c0][2j+1], -D_l[c1][2j+1] )   where -D_0 = -z0_0, -D_l = z0_{l-1}-z0_l
__device__ ulonglong2 g_negD2[LL * 8 * 8];
__device__ ulonglong2 g_m52[8 * 8];          // (z0_5 - mean), same interleave
__device__ ulonglong2 g_parab[LL * 8];       // {(a_c0,a_c1), (b_c0,b_c1)}
__device__ u64        g_parc[LL * 8];        // (a*b) pair
__device__ u64        g_hld2[8];             // half_logdet pair
__device__ float      g_hld[CC];
__device__ float      g_Linv[CC * DIMN * DIMN];
__device__ int        g_ident;

// ---------------- f32x2 packed helpers (sm_103a) -------------------
__device__ __forceinline__ u64 pk2(float lo, float hi) {
    u64 r; asm("mov.b64 %0, {%1, %2};" : "=l"(r) : "f"(lo), "f"(hi)); return r;
}
__device__ __forceinline__ void up2(float& lo, float& hi, u64 v) {
    asm("mov.b64 {%0, %1}, %2;" : "=f"(lo), "=f"(hi) : "l"(v));
}
__device__ __forceinline__ u64 ffma2(u64 a, u64 b, u64 c) {
    u64 d; asm("fma.rn.f32x2 %0, %1, %2, %3;" : "=l"(d) : "l"(a), "l"(b), "l"(c)); return d;
}
__device__ __forceinline__ u64 add2(u64 a, u64 b) {
    u64 d; asm("add.rn.f32x2 %0, %1, %2;" : "=l"(d) : "l"(a), "l"(b)); return d;
}
__device__ __forceinline__ u64 mul2(u64 a, u64 b) {
    u64 d; asm("mul.rn.f32x2 %0, %1, %2;" : "=l"(d) : "l"(a), "l"(b)); return d;
}
__device__ __forceinline__ float fast_sqrt(float x) {
    float r; asm("sqrt.approx.f32 %0, %1;" : "=f"(r) : "f"(x)); return r;
}
__device__ __forceinline__ float fast_rcp(float x) {
    float r; asm("rcp.approx.f32 %0, %1;" : "=f"(r) : "f"(x)); return r;
}

// ---------------- setup kernel ----------------
__global__ void setup_kernel(const float* __restrict__ la, const float* __restrict__ be,
                             const float* __restrict__ z0, const float* __restrict__ mean,
                             const float* __restrict__ cov) {
    __shared__ int s_bad;
    int t = threadIdx.x;
    if (t == 0) s_bad = 0;
    __syncthreads();

    // packed params per (layer, c-pair)
    for (int i = t; i < LL * 8; i += 256) {
        int l = i / 8, cp = i % 8;
        int c0 = 2 * cp, c1 = c0 + 1;
        float a0 = expf(la[l * CC + c0]), a1 = expf(la[l * CC + c1]);
        float b0 = be[l * CC + c0],       b1 = be[l * CC + c1];
        ulonglong2 v; v.x = pk2(a0, a1); v.y = pk2(b0, b1);
        g_parab[i] = v;
        g_parc[i]  = pk2(a0 * b0, a1 * b1);
    }
    // layer deltas, c-interleaved
    for (int i = t; i < LL * 8 * 8; i += 256) {
        int l = i / 64, rem = i % 64, cp = rem / 8, j = rem % 8;
        int c0 = 2 * cp, c1 = c0 + 1;
        int b0 = (l * CC + c0) * DIMN + 2 * j;
        int b1 = (l * CC + c1) * DIMN + 2 * j;
        float x0 = -z0[b0], y0 = -z0[b0 + 1];
        float x1 = -z0[b1], y1 = -z0[b1 + 1];
        if (l > 0) {
            int p0 = ((l - 1) * CC + c0) * DIMN + 2 * j;
            int p1 = ((l - 1) * CC + c1) * DIMN + 2 * j;
            x0 += z0[p0]; y0 += z0[p0 + 1];
            x1 += z0[p1]; y1 += z0[p1 + 1];
        }
        ulonglong2 v; v.x = pk2(x0, x1); v.y = pk2(y0, y1);
        g_negD2[i] = v;
    }
    // final offset: z0_5 - mean, c-interleaved
    for (int i = t; i < 8 * 8; i += 256) {
        int cp = i / 8, j = i % 8;
        int c0 = 2 * cp, c1 = c0 + 1;
        int b0 = (5 * CC + c0) * DIMN + 2 * j;
        int b1 = (5 * CC + c1) * DIMN + 2 * j;
        int m0 = c0 * DIMN + 2 * j, m1 = c1 * DIMN + 2 * j;
        ulonglong2 v;
        v.x = pk2(z0[b0]     - mean[m0],     z0[b1]     - mean[m1]);
        v.y = pk2(z0[b0 + 1] - mean[m0 + 1], z0[b1 + 1] - mean[m1 + 1]);
        g_m52[i] = v;
    }

    int bad = 0;
    for (int i = t; i < CC * DIMN * DIMN; i += 256) {
        float e = (((i % (DIMN * DIMN)) % (DIMN + 1)) == 0) ? 1.0f : 0.0f;
        if (cov[i] != e) bad = 1;
    }
    if (bad) atomicOr(&s_bad, 1);
    __syncthreads();
    int id = (s_bad == 0) ? 1 : 0;
    if (t == 0) g_ident = id;

    int c = t;
    if (c < CC) {
        if (id) {
            g_hld[c] = 0.0f;
        } else {
            // general Cholesky + triangular inverse (cold path)
            float Lm[DIMN][DIMN];
            const float* A = cov + c * DIMN * DIMN;
            #pragma unroll 1
            for (int j = 0; j < DIMN; j++) {
                float s = A[j * DIMN + j];
                #pragma unroll 1
                for (int k = 0; k < j; k++) s -= Lm[j][k] * Lm[j][k];
                float d = sqrtf(s);
                Lm[j][j] = d;
                float inv = 1.0f / d;
                #pragma unroll 1
                for (int i = j + 1; i < DIMN; i++) {
                    float s2 = A[i * DIMN + j];
                    #pragma unroll 1
                    for (int k = 0; k < j; k++) s2 -= Lm[i][k] * Lm[j][k];
                    Lm[i][j] = s2 * inv;
                }
            }
            float hld = 0.0f;
            #pragma unroll 1
            for (int j = 0; j < DIMN; j++) hld += logf(Lm[j][j]);
            g_hld[c] = hld;

            float Li[DIMN][DIMN];
            #pragma unroll 1
            for (int j = 0; j < DIMN; j++) {
                for (int i = 0; i < DIMN; i++) Li[i][j] = 0.0f;
                Li[j][j] = 1.0f / Lm[j][j];
                #pragma unroll 1
                for (int i = j + 1; i < DIMN; i++) {
                    float s3 = 0.0f;
                    #pragma unroll 1
                    for (int k = j; k < i; k++) s3 += Lm[i][k] * Li[k][j];
                    Li[i][j] = -s3 / Lm[i][i];
                }
            }
            for (int i = 0; i < DIMN; i++)
                for (int j = 0; j < DIMN; j++)
                    g_Linv[(c * DIMN + i) * DIMN + j] = Li[i][j];
        }
    }
    __syncthreads();
    if (t < 8) g_hld2[t] = pk2(g_hld[2 * t], g_hld[2 * t + 1]);
}

// ---------------- main density kernel ----------------
__global__ void __launch_bounds__(128)
density_kernel(const float* __restrict__ z, float* __restrict__ out, int N)
{
    __shared__ ulonglong2 s_negD[LL * 8 * 8];     // 6 KB
    __shared__ ulonglong2 s_m5[8 * 8];            // 1 KB
    __shared__ ulonglong2 s_parab[LL * 8];        // 768 B
    __shared__ u64        s_parc[LL * 8];         // 384 B
    __shared__ u64        s_hld2[8];
    __shared__ float      s_Linv[CC * DIMN * DIMN]; // 16 KB (used only if !ident)

    int t = threadIdx.x;
    for (int i = t; i < LL * 8 * 8; i += 128) s_negD[i] = g_negD2[i];
    if (t < 8 * 8) s_m5[t] = g_m52[t];
    if (t < LL * 8) { s_parab[t] = g_parab[t]; s_parc[t] = g_parc[t]; }
    if (t < 8) s_hld2[t] = g_hld2[t];
    int ident = g_ident;
    if (!ident)
        for (int i = t; i < CC * DIMN * DIMN; i += 128) s_Linv[i] = g_Linv[i];
    __syncthreads();

    int n = blockIdx.x * 128 + t;
    if (n >= N) return;

    // z row, held as 16 broadcast pairs (z[d], z[d]) for the whole thread lifetime
    const float4* zr = (const float4*)(z + (size_t)n * DIMN);
    float4 q0 = zr[0], q1 = zr[1], q2 = zr[2], q3 = zr[3];
    u64 zz[16];
    zz[0]  = pk2(q0.x, q0.x); zz[1]  = pk2(q0.y, q0.y);
    zz[2]  = pk2(q0.z, q0.z); zz[3]  = pk2(q0.w, q0.w);
    zz[4]  = pk2(q1.x, q1.x); zz[5]  = pk2(q1.y, q1.y);
    zz[6]  = pk2(q1.z, q1.z); zz[7]  = pk2(q1.w, q1.w);
    zz[8]  = pk2(q2.x, q2.x); zz[9]  = pk2(q2.y, q2.y);
    zz[10] = pk2(q2.z, q2.z); zz[11] = pk2(q2.w, q2.w);
    zz[12] = pk2(q3.x, q3.x); zz[13] = pk2(q3.y, q3.y);
    zz[14] = pk2(q3.z, q3.z); zz[15] = pk2(q3.w, q3.w);

    const float HALF_DIM_LOG2PI = 14.7030165f;   // 0.5 * 16 * log(2*pi)
    const u64 ONE2 = pk2(1.0f, 1.0f);
    float4* op = (float4*)(out + (size_t)n * CC);
    float vprev0 = 0.0f, vprev1 = 0.0f;

    #pragma unroll 1
    for (int cp = 0; cp < 8; cp++) {
        const ulonglong2* dp = &s_negD[cp * 8];   // layer stride: 8*8 = 64 ulonglong2

        u64 s[16];
        u64 P1p = ONE2, P2p = ONE2;
        u64 f1p;

        // ---- layer 0: s = z - z0_0 ----
        {
            u64 e0 = 0ull, e1 = 0ull, e2 = 0ull, e3 = 0ull;
            #pragma unroll
            for (int j = 0; j < 8; j++) {
                ulonglong2 dd = dp[j];
                s[2 * j]     = add2(zz[2 * j],     dd.x);
                s[2 * j + 1] = add2(zz[2 * j + 1], dd.y);
                if (j & 1) { e2 = ffma2(s[2 * j], s[2 * j], e2); e3 = ffma2(s[2 * j + 1], s[2 * j + 1], e3); }
                else       { e0 = ffma2(s[2 * j], s[2 * j], e0); e1 = ffma2(s[2 * j + 1], s[2 * j + 1], e1); }
            }
            u64 r2p = add2(add2(e0, e1), add2(e2, e3));   // (r2_c0, r2_c1)
            float r2A, r2B; up2(r2A, r2B, r2p);
            u64 rp = pk2(fast_sqrt(r2A), fast_sqrt(r2B));
            ulonglong2 pab = s_parab[cp];
            u64 upad = add2(pab.x, rp);                   // alpha + r
            float uA, uB; up2(uA, uB, upad);
            u64 hp = pk2(fast_rcp(uA), fast_rcp(uB));
            f1p = ffma2(pab.y, hp, ONE2);                 // (1+b*h) pair
            u64 f2p = ffma2(s_parc[cp], mul2(hp, hp), ONE2);
            P1p = mul2(P1p, f1p);
            P2p = mul2(P2p, f2p);
        }

        // ---- layers 1..5: s' = f1*s + (z0_{l-1} - z0_l); f1p used directly ----
        #pragma unroll
        for (int l = 1; l < LL; l++) {
            const ulonglong2* dl = dp + l * 64;
            u64 e0 = 0ull, e1 = 0ull, e2 = 0ull, e3 = 0ull;
            #pragma unroll
            for (int j = 0; j < 8; j++) {
                ulonglong2 dd = dl[j];
                s[2 * j]     = ffma2(f1p, s[2 * j],     dd.x);
                s[2 * j + 1] = ffma2(f1p, s[2 * j + 1], dd.y);
                if (j & 1) { e2 = ffma2(s[2 * j], s[2 * j], e2); e3 = ffma2(s[2 * j + 1], s[2 * j + 1], e3); }
                else       { e0 = ffma2(s[2 * j], s[2 * j], e0); e1 = ffma2(s[2 * j + 1], s[2 * j + 1], e1); }
            }
            u64 r2p = add2(add2(e0, e1), add2(e2, e3));
            float r2A, r2B; up2(r2A, r2B, r2p);
            u64 rp = pk2(fast_sqrt(r2A), fast_sqrt(r2B));
            ulonglong2 pab = s_parab[l * 8 + cp];
            u64 upad = add2(pab.x, rp);
            float uA, uB; up2(uA, uB, upad);
            u64 hp = pk2(fast_rcp(uA), fast_rcp(uB));
            f1p = ffma2(pab.y, hp, ONE2);
            u64 f2p = ffma2(s_parc[l * 8 + cp], mul2(hp, hp), ONE2);
            P1p = mul2(P1p, f1p);
            P2p = mul2(P2p, f2p);
        }

        // ---- final: diff = f1_5*s_5 + (z0_5 - mean); q = sum diff^2 ----
        const ulonglong2* mp = &s_m5[cp * 8];
        float qA, qB;
        if (ident) {
            u64 a0 = 0ull, a1 = 0ull, a2 = 0ull, a3 = 0ull;
            #pragma unroll
            for (int j = 0; j < 8; j++) {
                ulonglong2 mm = mp[j];
                u64 dx = ffma2(f1p, s[2 * j],     mm.x);
                u64 dy = ffma2(f1p, s[2 * j + 1], mm.y);
                if (j & 1) { a2 = ffma2(dx, dx, a2); a3 = ffma2(dy, dy, a3); }
                else       { a0 = ffma2(dx, dx, a0); a1 = ffma2(dy, dy, a1); }
            }
            u64 qp = add2(add2(a0, a1), add2(a2, a3));
            up2(qA, qB, qp);
        } else {
            float drA[DIMN], drB[DIMN];
            #pragma unroll
            for (int j = 0; j < 8; j++) {
                ulonglong2 mm = mp[j];
                u64 dx = ffma2(f1p, s[2 * j],     mm.x);
                u64 dy = ffma2(f1p, s[2 * j + 1], mm.y);
                up2(drA[2 * j],     drB[2 * j],     dx);
                up2(drA[2 * j + 1], drB[2 * j + 1], dy);
            }
            qA = 0.0f; qB = 0.0f;
            const float* LpA = &s_Linv[2 * cp * DIMN * DIMN];
            const float* LpB = LpA + DIMN * DIMN;
            #pragma unroll 1
            for (int j = 0; j < DIMN; j++) {
                float sa = 0.0f, sb = 0.0f;
                #pragma unroll 1
                for (int i = 0; i <= j; i++) {
                    sa = fmaf(LpA[j * DIMN + i], drA[i], sa);
                    sb = fmaf(LpB[j * DIMN + i], drB[i], sb);
                }
                qA = fmaf(sa, sa, qA);
                qB = fmaf(sb, sb, qB);
            }
        }

        // log_det_jac total = log(P1^15 * P2), packed pow15
        u64 p2  = mul2(P1p, P1p);
        u64 p4  = mul2(p2, p2);
        u64 p8  = mul2(p4, p4);
        u64 p15 = mul2(mul2(p8, p4), mul2(p2, P1p));
        u64 g   = mul2(p15, P2p);
        float gA, gB; up2(gA, gB, g);
        float hldA, hldB; up2(hldA, hldB, s_hld2[cp]);
        float vA = fmaf(-0.5f, qA, -HALF_DIM_LOG2PI) - hldA + __logf(gA);
        float vB = fmaf(-0.5f, qB, -HALF_DIM_LOG2PI) - hldB + __logf(gB);
        if (vA != vA) vA = __int_as_float(0xff800000);  // NaN -> -inf
        if (vB != vB) vB = __int_as_float(0xff800000);

        if (cp & 1) {
            op[cp >> 1] = make_float4(vprev0, vprev1, vA, vB);
        } else {
            vprev0 = vA; vprev1 = vB;
        }
    }
}

// ---------------- launch ----------------
extern "C" void kernel_launch(void* const* d_in, const int* in_sizes, int n_in,
                              void* d_out, int out_size) {
    const float* z    = (const float*)d_in[0];
    const float* z0   = (const float*)d_in[1];
    const float* la   = (const float*)d_in[2];
    const float* be   = (const float*)d_in[3];
    const float* mean = (const float*)d_in[4];
    const float* cov  = (const float*)d_in[5];
    float* out = (float*)d_out;

    int N = in_sizes[0] / DIMN;

    setup_kernel<<<1, 256>>>(la, be, z0, mean, cov);
    int blocks = (N + 127) / 128;
    density_kernel<<<blocks, 128>>>(z, out, N);
}